// round 10
// baseline (speedup 1.0000x reference)
#include <cuda_runtime.h>
#include <cuda_bf16.h>
#include <cstdint>

// ---------------------------------------------------------------------------
// vGINMolEncoder: 5-layer GINEConv + virtual node, eval-mode BN, mean-pool.
// GEMMs: 3xTF32 mma.sync. Weights pre-split (hi/lo) in GMEM; activations
// split in registers. Product set identical to the R4-passing kernel:
//   D += Ah*Bl + Al*Bh + Ah*Bh   (fp32 accumulate)
// ---------------------------------------------------------------------------

#define MAXN 200000
#define MAXG 8000
#define DIM  300
#define HID  600
#define NLAYER 5
#define EPS_BN 1e-5f
#define C4 75            // DIM / 4

__device__ __align__(256) float g_h     [(size_t)MAXN * DIM];
__device__ __align__(256) float g_aggr  [(size_t)MAXN * DIM];
__device__ __align__(256) float g_hid   [(size_t)MAXN * HID];
__device__ __align__(256) float g_post  [(size_t)MAXN * DIM];
__device__ __align__(256) float g_vfeat [(size_t)MAXG * DIM];
__device__ __align__(256) float g_pooled[(size_t)MAXG * DIM];
__device__ __align__(256) float g_vhid  [(size_t)MAXG * HID];
__device__ __align__(256) float g_cnt   [MAXG];
// hi/lo split weights, same [K][Nc] row-major layout as the originals
__device__ __align__(256) float g_W1h [(size_t)NLAYER * DIM * HID];
__device__ __align__(256) float g_W1l [(size_t)NLAYER * DIM * HID];
__device__ __align__(256) float g_W2h [(size_t)NLAYER * HID * DIM];
__device__ __align__(256) float g_W2l [(size_t)NLAYER * HID * DIM];
__device__ __align__(256) float g_vW1h[(size_t)DIM * HID];
__device__ __align__(256) float g_vW1l[(size_t)DIM * HID];
__device__ __align__(256) float g_vW2h[(size_t)HID * DIM];
__device__ __align__(256) float g_vW2l[(size_t)HID * DIM];

// ---------------------------------------------------------------------------
// Elementwise / scatter kernels (unchanged, proven)
// ---------------------------------------------------------------------------
__global__ void atom_encode_kernel(const int* __restrict__ x,
                                   const float* __restrict__ atom_emb,
                                   float* __restrict__ h,
                                   float* __restrict__ aggr, int N) {
    int idx = blockIdx.x * blockDim.x + threadIdx.x;
    if (idx >= N * C4) return;
    int n = idx / C4;
    int c = (idx - n * C4) * 4;
    float4 s = make_float4(0.f, 0.f, 0.f, 0.f);
#pragma unroll
    for (int f = 0; f < 9; f++) {
        int v = x[n * 9 + f];
        const float4 e = *(const float4*)(atom_emb + ((size_t)(f * 64 + v)) * DIM + c);
        s.x += e.x; s.y += e.y; s.z += e.z; s.w += e.w;
    }
    *(float4*)(h    + (size_t)n * DIM + c) = s;
    *(float4*)(aggr + (size_t)n * DIM + c) = s;
}

__global__ void edge_msg_kernel(const float* __restrict__ h,
                                const int* __restrict__ src,
                                const int* __restrict__ dst,
                                const int* __restrict__ ea,
                                const float* __restrict__ bond_l,
                                float* __restrict__ aggr, int E) {
    int idx = blockIdx.x * blockDim.x + threadIdx.x;
    if (idx >= E * C4) return;
    int e  = idx / C4;
    int c  = (idx - e * C4) * 4;
    int s  = src[e];
    int dn = dst[e];
    int a0 = ea[e * 3 + 0], a1 = ea[e * 3 + 1], a2 = ea[e * 3 + 2];
    const float4 b0 = *(const float4*)(bond_l + ((size_t)(0 * 16 + a0)) * DIM + c);
    const float4 b1 = *(const float4*)(bond_l + ((size_t)(1 * 16 + a1)) * DIM + c);
    const float4 b2 = *(const float4*)(bond_l + ((size_t)(2 * 16 + a2)) * DIM + c);
    const float4 hv = *(const float4*)(h + (size_t)s * DIM + c);
    float4 m;
    m.x = fmaxf(hv.x + b0.x + b1.x + b2.x, 0.f);
    m.y = fmaxf(hv.y + b0.y + b1.y + b2.y, 0.f);
    m.z = fmaxf(hv.z + b0.z + b1.z + b2.z, 0.f);
    m.w = fmaxf(hv.w + b0.w + b1.w + b2.w, 0.f);
    float* p = aggr + (size_t)dn * DIM + c;
    atomicAdd(p + 0, m.x);
    atomicAdd(p + 1, m.y);
    atomicAdd(p + 2, m.z);
    atomicAdd(p + 3, m.w);
}

__global__ void add_vfeat_kernel(const float* __restrict__ post,
                                 const float* __restrict__ vfeat,
                                 const int* __restrict__ batch,
                                 float* __restrict__ h,
                                 float* __restrict__ aggr, int N) {
    int idx = blockIdx.x * blockDim.x + threadIdx.x;
    if (idx >= N * C4) return;
    int n = idx / C4;
    int c = (idx - n * C4) * 4;
    int g = batch[n];
    const float4 p = *(const float4*)(post  + (size_t)n * DIM + c);
    const float4 v = *(const float4*)(vfeat + (size_t)g * DIM + c);
    float4 o = make_float4(p.x + v.x, p.y + v.y, p.z + v.z, p.w + v.w);
    *(float4*)(h    + (size_t)n * DIM + c) = o;
    *(float4*)(aggr + (size_t)n * DIM + c) = o;
}

__global__ void pool_kernel(const float* __restrict__ post,
                            const int* __restrict__ batch,
                            float* __restrict__ pooled, int N) {
    int idx = blockIdx.x * blockDim.x + threadIdx.x;
    if (idx >= N * C4) return;
    int n = idx / C4;
    int c = (idx - n * C4) * 4;
    int g = batch[n];
    const float4 p = *(const float4*)(post + (size_t)n * DIM + c);
    float* q = pooled + (size_t)g * DIM + c;
    atomicAdd(q + 0, p.x);
    atomicAdd(q + 1, p.y);
    atomicAdd(q + 2, p.z);
    atomicAdd(q + 3, p.w);
}

__global__ void count_kernel(const int* __restrict__ batch, float* __restrict__ cnt, int N) {
    int i = blockIdx.x * blockDim.x + threadIdx.x;
    if (i < N) atomicAdd(&cnt[batch[i]], 1.0f);
}

__global__ void vfeat_init_kernel(const float* __restrict__ vn, float* __restrict__ vfeat, int G) {
    int idx = blockIdx.x * blockDim.x + threadIdx.x;
    if (idx >= G * DIM) return;
    vfeat[idx] = vn[idx % DIM];
}

__global__ void copy_kernel(const float* __restrict__ src, float* __restrict__ dst, int n4) {
    int idx = blockIdx.x * blockDim.x + threadIdx.x;
    if (idx >= n4) return;
    *(float4*)(dst + idx * 4) = *(const float4*)(src + idx * 4);
}

__global__ void out_kernel(const float* __restrict__ pooled, const float* __restrict__ cnt,
                           float* __restrict__ out, int G) {
    int idx = blockIdx.x * blockDim.x + threadIdx.x;
    if (idx >= G * DIM) return;
    int g = idx / DIM;
    out[idx] = pooled[idx] / fmaxf(cnt[g], 1.0f);
}

// weights: W [K][Nc] -> Wh (tf32-truncated) and Wl (residual), same layout
__global__ void split_w_hl(const float* __restrict__ W, float* __restrict__ Wh,
                           float* __restrict__ Wl, int total) {
    int idx = blockIdx.x * blockDim.x + threadIdx.x;
    if (idx >= total) return;
    float v = W[idx];
    float hi = __uint_as_float(__float_as_uint(v) & 0xFFFFE000u);
    Wh[idx] = hi;
    Wl[idx] = v - hi;
}

// ---------------------------------------------------------------------------
// 3xTF32 GEMM, B pre-split (hi/lo streamed to smem), A split in registers.
// C = epi(A @ B + bias). A:[M,K] rm, Bh/Bl:[K,Nc] rm, bnp:[4,Nc].
// 128x128x16 tile, 256 threads (8 warps 4x2), warp 32x64, m16n8k8.
// ---------------------------------------------------------------------------
#define GBM 128
#define GBN 128
#define GBK 16
#define LDA 20    // GBK + 4 -> conflict-free A fragment loads
#define LDB 136   // GBN + 8 -> conflict-free B fragment loads
#define SM_AS 0                        // As [2][128][20]   = 5120 floats
#define SM_BH (2 * GBM * LDA)          // BsH[2][16][136]   = 4352 floats
#define SM_BL (SM_BH + 2 * GBK * LDB)  // BsL[2][16][136]   = 4352 floats
#define GEMM_SMEM_F (SM_BL + 2 * GBK * LDB)
#define GEMM_SMEM_B (GEMM_SMEM_F * 4)  // 55,296 bytes

__device__ __forceinline__ void cp_async16(uint32_t saddr, const void* gptr, int src_bytes) {
    asm volatile("cp.async.cg.shared.global [%0], [%1], 16, %2;\n"
                 :: "r"(saddr), "l"(gptr), "r"(src_bytes));
}
__device__ __forceinline__ void cp_commit() { asm volatile("cp.async.commit_group;\n" ::); }
template <int N>
__device__ __forceinline__ void cp_wait() { asm volatile("cp.async.wait_group %0;\n" :: "n"(N)); }

__device__ __forceinline__ void mma_tf32(float* d, const uint32_t* a, const uint32_t* b) {
    asm volatile(
        "mma.sync.aligned.m16n8k8.row.col.f32.tf32.tf32.f32 "
        "{%0,%1,%2,%3}, {%4,%5,%6,%7}, {%8,%9}, {%0,%1,%2,%3};\n"
        : "+f"(d[0]), "+f"(d[1]), "+f"(d[2]), "+f"(d[3])
        : "r"(a[0]), "r"(a[1]), "r"(a[2]), "r"(a[3]), "r"(b[0]), "r"(b[1]));
}

__device__ __forceinline__ void tf32_split(uint32_t v, uint32_t& hi, uint32_t& lo) {
    hi = v & 0xFFFFE000u;
    lo = __float_as_uint(__uint_as_float(v) - __uint_as_float(hi));
}

__global__ __launch_bounds__(256) void gemm_tf32_bn(
    const float* __restrict__ A, const float* __restrict__ Bh,
    const float* __restrict__ Bl,
    const float* __restrict__ bias, const float* __restrict__ bnp,
    float* __restrict__ C, int M, int K, int Nc, int do_relu) {

    extern __shared__ float smem[];
    float* As  = smem + SM_AS;   // [2][GBM][LDA]
    float* BsH = smem + SM_BH;   // [2][GBK][LDB]
    float* BsL = smem + SM_BL;   // [2][GBK][LDB]

    const int tid = threadIdx.x;
    const int w = tid >> 5, l = tid & 31;
    const int wm = (w & 3) * 32;
    const int wn = (w >> 2) * 64;
    const int m0 = blockIdx.y * GBM;
    const int n0 = blockIdx.x * GBN;
    const int iters = (K + GBK - 1) / GBK;

    const int qr = l >> 2;   // 0..7
    const int qc = l & 3;    // 0..3

    const int a_row = tid >> 2;
    const int a_kc  = (tid & 3) * 4;
    const int b_row = tid >> 5;
    const int b_nc  = (tid & 31) * 4;

    float acc[2][8][4];
#pragma unroll
    for (int mi = 0; mi < 2; mi++)
#pragma unroll
        for (int ni = 0; ni < 8; ni++)
#pragma unroll
            for (int r = 0; r < 4; r++) acc[mi][ni][r] = 0.f;

    auto issue_load = [&](int it, int buf) {
        const int k0 = it * GBK;
#pragma unroll
        for (int i = 0; i < 2; i++) {
            int row = a_row + i * 64;
            int gm = m0 + row, gk = k0 + a_kc;
            int ok = (gm < M) && (gk + 4 <= K);
            const float* src = A + (size_t)(ok ? gm : 0) * K + (ok ? gk : 0);
            uint32_t dst = (uint32_t)__cvta_generic_to_shared(
                &As[(size_t)buf * GBM * LDA + row * LDA + a_kc]);
            cp_async16(dst, src, ok ? 16 : 0);
        }
#pragma unroll
        for (int i = 0; i < 2; i++) {
            int row = b_row + i * 8;
            int gk = k0 + row, gn = n0 + b_nc;
            int ok = (gk < K) && (gn + 4 <= Nc);
            size_t goff = (size_t)(ok ? gk : 0) * Nc + (ok ? gn : 0);
            uint32_t dsth = (uint32_t)__cvta_generic_to_shared(
                &BsH[(size_t)buf * GBK * LDB + row * LDB + b_nc]);
            uint32_t dstl = (uint32_t)__cvta_generic_to_shared(
                &BsL[(size_t)buf * GBK * LDB + row * LDB + b_nc]);
            cp_async16(dsth, Bh + goff, ok ? 16 : 0);
            cp_async16(dstl, Bl + goff, ok ? 16 : 0);
        }
        cp_commit();
    };

    issue_load(0, 0);

    for (int it = 0; it < iters; it++) {
        const int buf = it & 1;
        if (it + 1 < iters) {
            issue_load(it + 1, buf ^ 1);
            cp_wait<1>();
        } else {
            cp_wait<0>();
        }
        __syncthreads();

#pragma unroll
        for (int ks = 0; ks < 2; ks++) {
            const int kb = ks * 8;
            uint32_t ah[2][4], al[2][4], bh[8][2], bl[8][2];
#pragma unroll
            for (int mi = 0; mi < 2; mi++) {
                const float* Ap = &As[(size_t)buf * GBM * LDA
                                      + (wm + mi * 16 + qr) * LDA + kb + qc];
                uint32_t v0 = __float_as_uint(Ap[0]);
                uint32_t v1 = __float_as_uint(Ap[8 * LDA]);
                uint32_t v2 = __float_as_uint(Ap[4]);
                uint32_t v3 = __float_as_uint(Ap[8 * LDA + 4]);
                tf32_split(v0, ah[mi][0], al[mi][0]);
                tf32_split(v1, ah[mi][1], al[mi][1]);
                tf32_split(v2, ah[mi][2], al[mi][2]);
                tf32_split(v3, ah[mi][3], al[mi][3]);
            }
#pragma unroll
            for (int ni = 0; ni < 8; ni++) {
                size_t off = (size_t)buf * GBK * LDB + (kb + qc) * LDB + wn + ni * 8 + qr;
                bh[ni][0] = __float_as_uint(BsH[off]);
                bh[ni][1] = __float_as_uint(BsH[off + 4 * LDB]);
                bl[ni][0] = __float_as_uint(BsL[off]);
                bl[ni][1] = __float_as_uint(BsL[off + 4 * LDB]);
            }
#pragma unroll
            for (int mi = 0; mi < 2; mi++)
#pragma unroll
                for (int ni = 0; ni < 8; ni++) {
                    mma_tf32(acc[mi][ni], ah[mi], bl[ni]);
                    mma_tf32(acc[mi][ni], al[mi], bh[ni]);
                    mma_tf32(acc[mi][ni], ah[mi], bh[ni]);
                }
        }
        __syncthreads();
    }

    // -------- epilogue: bias -> BN -> (ReLU) --------
#pragma unroll
    for (int ni = 0; ni < 8; ni++) {
        int col = n0 + wn + ni * 8 + qc * 2;
        if (col >= Nc) continue;   // Nc even -> col+1 valid
        float bb0 = bias[col], bb1 = bias[col + 1];
        float ga0 = bnp[col],          be0 = bnp[Nc + col];
        float mu0 = bnp[2 * Nc + col], va0 = bnp[3 * Nc + col];
        float ga1 = bnp[col + 1],          be1 = bnp[Nc + col + 1];
        float mu1 = bnp[2 * Nc + col + 1], va1 = bnp[3 * Nc + col + 1];
        float s0 = ga0 * rsqrtf(va0 + EPS_BN), t0 = be0 - mu0 * s0;
        float s1 = ga1 * rsqrtf(va1 + EPS_BN), t1 = be1 - mu1 * s1;
#pragma unroll
        for (int mi = 0; mi < 2; mi++) {
#pragma unroll
            for (int r = 0; r < 2; r++) {
                int row = m0 + wm + mi * 16 + qr + r * 8;
                if (row >= M) continue;
                float v0 = (acc[mi][ni][r * 2 + 0] + bb0) * s0 + t0;
                float v1 = (acc[mi][ni][r * 2 + 1] + bb1) * s1 + t1;
                if (do_relu) { v0 = fmaxf(v0, 0.f); v1 = fmaxf(v1, 0.f); }
                *(float2*)(C + (size_t)row * Nc + col) = make_float2(v0, v1);
            }
        }
    }
}

static void run_gemm(const float* A, const float* Bh, const float* Bl,
                     const float* bias, const float* bnp, float* C,
                     int M, int K, int Nc, int do_relu) {
    dim3 grid((Nc + GBN - 1) / GBN, (M + GBM - 1) / GBM);
    gemm_tf32_bn<<<grid, 256, GEMM_SMEM_B>>>(A, Bh, Bl, bias, bnp, C, M, K, Nc, do_relu);
}

// ---------------------------------------------------------------------------
// kernel_launch
// ---------------------------------------------------------------------------
extern "C" void kernel_launch(void* const* d_in, const int* in_sizes, int n_in,
                              void* d_out, int out_size) {
    const int*   x         = (const int*)  d_in[0];
    const int*   edge_idx  = (const int*)  d_in[1];
    const int*   edge_attr = (const int*)  d_in[2];
    const int*   batch     = (const int*)  d_in[3];
    const float* atom_emb  = (const float*)d_in[4];
    const float* bond_emb  = (const float*)d_in[5];
    const float* W1        = (const float*)d_in[6];
    const float* b1        = (const float*)d_in[7];
    const float* bn_in     = (const float*)d_in[8];
    const float* W2        = (const float*)d_in[9];
    const float* b2        = (const float*)d_in[10];
    const float* bn_out    = (const float*)d_in[11];
    const float* vn        = (const float*)d_in[12];
    const float* vW1       = (const float*)d_in[13];
    const float* vb1       = (const float*)d_in[14];
    const float* vbn1      = (const float*)d_in[15];
    const float* vW2       = (const float*)d_in[16];
    const float* vb2       = (const float*)d_in[17];
    const float* vbn2      = (const float*)d_in[18];
    float*       out       = (float*)d_out;

    const int N = in_sizes[0] / 9;
    const int E = in_sizes[1] / 2;
    const int G = out_size / DIM;

    float *h, *aggr, *hid, *post, *vfeat, *pooled, *vhid, *cnt;
    float *W1h, *W1l, *W2h, *W2l, *vW1h, *vW1l, *vW2h, *vW2l;
    cudaGetSymbolAddress((void**)&h,      g_h);
    cudaGetSymbolAddress((void**)&aggr,   g_aggr);
    cudaGetSymbolAddress((void**)&hid,    g_hid);
    cudaGetSymbolAddress((void**)&post,   g_post);
    cudaGetSymbolAddress((void**)&vfeat,  g_vfeat);
    cudaGetSymbolAddress((void**)&pooled, g_pooled);
    cudaGetSymbolAddress((void**)&vhid,   g_vhid);
    cudaGetSymbolAddress((void**)&cnt,    g_cnt);
    cudaGetSymbolAddress((void**)&W1h,    g_W1h);
    cudaGetSymbolAddress((void**)&W1l,    g_W1l);
    cudaGetSymbolAddress((void**)&W2h,    g_W2h);
    cudaGetSymbolAddress((void**)&W2l,    g_W2l);
    cudaGetSymbolAddress((void**)&vW1h,   g_vW1h);
    cudaGetSymbolAddress((void**)&vW1l,   g_vW1l);
    cudaGetSymbolAddress((void**)&vW2h,   g_vW2h);
    cudaGetSymbolAddress((void**)&vW2l,   g_vW2l);

    cudaFuncSetAttribute(gemm_tf32_bn, cudaFuncAttributeMaxDynamicSharedMemorySize,
                         GEMM_SMEM_B);

    const int* src = edge_idx;
    const int* dst = edge_idx + E;

    const int TPB = 256;
    const int nodeC4Blocks = (N * C4 + TPB - 1) / TPB;
    const int edgeC4Blocks = (E * C4 + TPB - 1) / TPB;

    // ---- per-call weight prep: split into hi/lo (same layout) ----
    {
        int t1 = NLAYER * DIM * HID;
        int t2 = NLAYER * HID * DIM;
        int tv = DIM * HID;
        split_w_hl<<<(t1 + TPB - 1) / TPB, TPB>>>(W1, W1h, W1l, t1);
        split_w_hl<<<(t2 + TPB - 1) / TPB, TPB>>>(W2, W2h, W2l, t2);
        split_w_hl<<<(tv + TPB - 1) / TPB, TPB>>>(vW1, vW1h, vW1l, tv);
        split_w_hl<<<(tv + TPB - 1) / TPB, TPB>>>(vW2, vW2h, vW2l, tv);
    }

    atom_encode_kernel<<<nodeC4Blocks, TPB>>>(x, atom_emb, h, aggr, N);
    vfeat_init_kernel<<<(G * DIM + TPB - 1) / TPB, TPB>>>(vn, vfeat, G);
    cudaMemsetAsync(cnt, 0, (size_t)G * sizeof(float));
    count_kernel<<<(N + TPB - 1) / TPB, TPB>>>(batch, cnt, N);

    for (int l = 0; l < NLAYER; l++) {
        if (l > 0)
            add_vfeat_kernel<<<nodeC4Blocks, TPB>>>(post, vfeat, batch, h, aggr, N);

        // aggr holds h; edge atomics produce z = h + sum(msg)
        edge_msg_kernel<<<edgeC4Blocks, TPB>>>(
            h, src, dst, edge_attr, bond_emb + (size_t)l * 3 * 16 * DIM, aggr, E);

        // hid = relu(bn_in(z @ W1 + b1))
        run_gemm(aggr, W1h + (size_t)l * DIM * HID, W1l + (size_t)l * DIM * HID,
                 b1 + (size_t)l * HID, bn_in + (size_t)l * 4 * HID, hid, N, DIM, HID, 1);
        // post = bn_out(hid @ W2 + b2) (+relu except last layer)
        run_gemm(hid, W2h + (size_t)l * HID * DIM, W2l + (size_t)l * HID * DIM,
                 b2 + (size_t)l * DIM, bn_out + (size_t)l * 4 * DIM, post, N, HID, DIM,
                 (l < NLAYER - 1) ? 1 : 0);

        if (l >= 1 && l < NLAYER - 1) {
            copy_kernel<<<(G * C4 + TPB - 1) / TPB, TPB>>>(vfeat, pooled, G * C4);
            pool_kernel<<<nodeC4Blocks, TPB>>>(post, batch, pooled, N);
            run_gemm(pooled, vW1h, vW1l, vb1, vbn1, vhid, G, DIM, HID, 1);
            run_gemm(vhid, vW2h, vW2l, vb2, vbn2, vfeat, G, HID, DIM, 1);
        }
    }

    cudaMemsetAsync(pooled, 0, (size_t)G * DIM * sizeof(float));
    pool_kernel<<<nodeC4Blocks, TPB>>>(post, batch, pooled, N);
    out_kernel<<<(G * DIM + TPB - 1) / TPB, TPB>>>(pooled, cnt, out, G);
}

// round 14
// speedup vs baseline: 1.2176x; 1.2176x over previous
#include <cuda_runtime.h>
#include <cuda_bf16.h>
#include <cstdint>

// ---------------------------------------------------------------------------
// vGINMolEncoder: 5-layer GINEConv + virtual node, eval-mode BN, mean-pool.
// GEMMs: bf16x3 error-compensated mma.sync.m16n8k16 (fp32 accumulate).
//   weights pre-split hi/lo bf16, transposed [Nc][Kpad]; activations split
//   to bf16 in registers.  D += Ah*Bl + Al*Bh + Ah*Bh.
// ---------------------------------------------------------------------------

#define MAXN 200000
#define MAXG 8000
#define DIM  300
#define HID  600
#define NLAYER 5
#define EPS_BN 1e-5f
#define C4 75            // DIM / 4
#define KPAD1 304        // DIM padded to 16
#define KPAD2 608        // HID padded to 16

__device__ __align__(256) float g_h     [(size_t)MAXN * DIM];
__device__ __align__(256) float g_aggr  [(size_t)MAXN * DIM];
__device__ __align__(256) float g_hid   [(size_t)MAXN * HID];
__device__ __align__(256) float g_post  [(size_t)MAXN * DIM];
__device__ __align__(256) float g_vfeat [(size_t)MAXG * DIM];
__device__ __align__(256) float g_pooled[(size_t)MAXG * DIM];
__device__ __align__(256) float g_vhid  [(size_t)MAXG * HID];
__device__ __align__(256) float g_cnt   [MAXG];
// bf16 hi/lo split weights, transposed: [Nc][Kpad]
__device__ __align__(256) __nv_bfloat16 g_W1h [(size_t)NLAYER * HID * KPAD1];
__device__ __align__(256) __nv_bfloat16 g_W1l [(size_t)NLAYER * HID * KPAD1];
__device__ __align__(256) __nv_bfloat16 g_W2h [(size_t)NLAYER * DIM * KPAD2];
__device__ __align__(256) __nv_bfloat16 g_W2l [(size_t)NLAYER * DIM * KPAD2];
__device__ __align__(256) __nv_bfloat16 g_vW1h[(size_t)HID * KPAD1];
__device__ __align__(256) __nv_bfloat16 g_vW1l[(size_t)HID * KPAD1];
__device__ __align__(256) __nv_bfloat16 g_vW2h[(size_t)DIM * KPAD2];
__device__ __align__(256) __nv_bfloat16 g_vW2l[(size_t)DIM * KPAD2];

// ---------------------------------------------------------------------------
// Elementwise / scatter kernels (unchanged, proven)
// ---------------------------------------------------------------------------
__global__ void atom_encode_kernel(const int* __restrict__ x,
                                   const float* __restrict__ atom_emb,
                                   float* __restrict__ h,
                                   float* __restrict__ aggr, int N) {
    int idx = blockIdx.x * blockDim.x + threadIdx.x;
    if (idx >= N * C4) return;
    int n = idx / C4;
    int c = (idx - n * C4) * 4;
    float4 s = make_float4(0.f, 0.f, 0.f, 0.f);
#pragma unroll
    for (int f = 0; f < 9; f++) {
        int v = x[n * 9 + f];
        const float4 e = *(const float4*)(atom_emb + ((size_t)(f * 64 + v)) * DIM + c);
        s.x += e.x; s.y += e.y; s.z += e.z; s.w += e.w;
    }
    *(float4*)(h    + (size_t)n * DIM + c) = s;
    *(float4*)(aggr + (size_t)n * DIM + c) = s;
}

__global__ void edge_msg_kernel(const float* __restrict__ h,
                                const int* __restrict__ src,
                                const int* __restrict__ dst,
                                const int* __restrict__ ea,
                                const float* __restrict__ bond_l,
                                float* __restrict__ aggr, int E) {
    int idx = blockIdx.x * blockDim.x + threadIdx.x;
    if (idx >= E * C4) return;
    int e  = idx / C4;
    int c  = (idx - e * C4) * 4;
    int s  = src[e];
    int dn = dst[e];
    int a0 = ea[e * 3 + 0], a1 = ea[e * 3 + 1], a2 = ea[e * 3 + 2];
    const float4 b0 = *(const float4*)(bond_l + ((size_t)(0 * 16 + a0)) * DIM + c);
    const float4 b1 = *(const float4*)(bond_l + ((size_t)(1 * 16 + a1)) * DIM + c);
    const float4 b2 = *(const float4*)(bond_l + ((size_t)(2 * 16 + a2)) * DIM + c);
    const float4 hv = *(const float4*)(h + (size_t)s * DIM + c);
    float4 m;
    m.x = fmaxf(hv.x + b0.x + b1.x + b2.x, 0.f);
    m.y = fmaxf(hv.y + b0.y + b1.y + b2.y, 0.f);
    m.z = fmaxf(hv.z + b0.z + b1.z + b2.z, 0.f);
    m.w = fmaxf(hv.w + b0.w + b1.w + b2.w, 0.f);
    float* p = aggr + (size_t)dn * DIM + c;
    atomicAdd(p + 0, m.x);
    atomicAdd(p + 1, m.y);
    atomicAdd(p + 2, m.z);
    atomicAdd(p + 3, m.w);
}

__global__ void add_vfeat_kernel(const float* __restrict__ post,
                                 const float* __restrict__ vfeat,
                                 const int* __restrict__ batch,
                                 float* __restrict__ h,
                                 float* __restrict__ aggr, int N) {
    int idx = blockIdx.x * blockDim.x + threadIdx.x;
    if (idx >= N * C4) return;
    int n = idx / C4;
    int c = (idx - n * C4) * 4;
    int g = batch[n];
    const float4 p = *(const float4*)(post  + (size_t)n * DIM + c);
    const float4 v = *(const float4*)(vfeat + (size_t)g * DIM + c);
    float4 o = make_float4(p.x + v.x, p.y + v.y, p.z + v.z, p.w + v.w);
    *(float4*)(h    + (size_t)n * DIM + c) = o;
    *(float4*)(aggr + (size_t)n * DIM + c) = o;
}

__global__ void pool_kernel(const float* __restrict__ post,
                            const int* __restrict__ batch,
                            float* __restrict__ pooled, int N) {
    int idx = blockIdx.x * blockDim.x + threadIdx.x;
    if (idx >= N * C4) return;
    int n = idx / C4;
    int c = (idx - n * C4) * 4;
    int g = batch[n];
    const float4 p = *(const float4*)(post + (size_t)n * DIM + c);
    float* q = pooled + (size_t)g * DIM + c;
    atomicAdd(q + 0, p.x);
    atomicAdd(q + 1, p.y);
    atomicAdd(q + 2, p.z);
    atomicAdd(q + 3, p.w);
}

__global__ void count_kernel(const int* __restrict__ batch, float* __restrict__ cnt, int N) {
    int i = blockIdx.x * blockDim.x + threadIdx.x;
    if (i < N) atomicAdd(&cnt[batch[i]], 1.0f);
}

__global__ void vfeat_init_kernel(const float* __restrict__ vn, float* __restrict__ vfeat, int G) {
    int idx = blockIdx.x * blockDim.x + threadIdx.x;
    if (idx >= G * DIM) return;
    vfeat[idx] = vn[idx % DIM];
}

__global__ void copy_kernel(const float* __restrict__ src, float* __restrict__ dst, int n4) {
    int idx = blockIdx.x * blockDim.x + threadIdx.x;
    if (idx >= n4) return;
    *(float4*)(dst + idx * 4) = *(const float4*)(src + idx * 4);
}

__global__ void out_kernel(const float* __restrict__ pooled, const float* __restrict__ cnt,
                           float* __restrict__ out, int G) {
    int idx = blockIdx.x * blockDim.x + threadIdx.x;
    if (idx >= G * DIM) return;
    int g = idx / DIM;
    out[idx] = pooled[idx] / fmaxf(cnt[g], 1.0f);
}

// W [K][Nc] row-major -> Wh/Wl [Nc][Kpad] bf16 (hi = rn_bf16(v), lo = rn_bf16(v-hi))
__global__ void split_w_t(const float* __restrict__ W, __nv_bfloat16* __restrict__ Wh,
                          __nv_bfloat16* __restrict__ Wl, int K, int Nc, int Kpad) {
    int idx = blockIdx.x * blockDim.x + threadIdx.x;
    if (idx >= Nc * Kpad) return;
    int n = idx / Kpad;
    int k = idx - n * Kpad;
    float v = (k < K) ? W[(size_t)k * Nc + n] : 0.f;
    __nv_bfloat16 hh = __float2bfloat16_rn(v);
    __nv_bfloat16 ll = __float2bfloat16_rn(v - __bfloat162float(hh));
    Wh[idx] = hh;
    Wl[idx] = ll;
}

// ---------------------------------------------------------------------------
// bf16x3 GEMM with fused BN(+ReLU) epilogue.
// C = epi(A @ W + bias). A:[M,K] fp32 rm; Wh/Wl:[Nc][Kpad] bf16 (K-major);
// bnp:[4,Nc]. 128x128 tile, K-tile 16, 256 threads (8 warps 4x2),
// warp tile 32x64, mma m16n8k16.
// ---------------------------------------------------------------------------
#define GBM 128
#define GBN 128
#define LDA 20    // fp32 A row stride (16 + 4)
#define LDBH 24   // bf16 B row stride (16 + 8): 12*qr mod 32 hits all banks once

__device__ __forceinline__ void cp_async16(uint32_t saddr, const void* gptr, int src_bytes) {
    asm volatile("cp.async.cg.shared.global [%0], [%1], 16, %2;\n"
                 :: "r"(saddr), "l"(gptr), "r"(src_bytes));
}
__device__ __forceinline__ void cp_commit() { asm volatile("cp.async.commit_group;\n" ::); }
template <int N>
__device__ __forceinline__ void cp_wait() { asm volatile("cp.async.wait_group %0;\n" :: "n"(N)); }

__device__ __forceinline__ void mma_bf16(float* d, const uint32_t* a, const uint32_t* b) {
    asm volatile(
        "mma.sync.aligned.m16n8k16.row.col.f32.bf16.bf16.f32 "
        "{%0,%1,%2,%3}, {%4,%5,%6,%7}, {%8,%9}, {%0,%1,%2,%3};\n"
        : "+f"(d[0]), "+f"(d[1]), "+f"(d[2]), "+f"(d[3])
        : "r"(a[0]), "r"(a[1]), "r"(a[2]), "r"(a[3]), "r"(b[0]), "r"(b[1]));
}

// split one float2 into packed bf16 hi-pair and lo-pair (element0 in low bits)
__device__ __forceinline__ void split_pack(float2 v, uint32_t& hi, uint32_t& lo) {
    __nv_bfloat16 hx = __float2bfloat16_rn(v.x), hy = __float2bfloat16_rn(v.y);
    __nv_bfloat16 lx = __float2bfloat16_rn(v.x - __bfloat162float(hx));
    __nv_bfloat16 ly = __float2bfloat16_rn(v.y - __bfloat162float(hy));
    __nv_bfloat162 H = __halves2bfloat162(hx, hy);
    __nv_bfloat162 L = __halves2bfloat162(lx, ly);
    hi = *(uint32_t*)&H;
    lo = *(uint32_t*)&L;
}

__global__ __launch_bounds__(256) void gemm_bf16x3_bn(
    const float* __restrict__ A, const __nv_bfloat16* __restrict__ Bh,
    const __nv_bfloat16* __restrict__ Bl,
    const float* __restrict__ bias, const float* __restrict__ bnp,
    float* __restrict__ C, int M, int K, int Kpad, int Nc, int do_relu) {

    __shared__ __align__(16) float         As [2][GBM][LDA];
    __shared__ __align__(16) __nv_bfloat16 BsH[2][GBN][LDBH];
    __shared__ __align__(16) __nv_bfloat16 BsL[2][GBN][LDBH];

    const int tid = threadIdx.x;
    const int w = tid >> 5, l = tid & 31;
    const int wm = (w & 3) * 32;
    const int wn = (w >> 2) * 64;
    const int m0 = blockIdx.y * GBM;
    const int n0 = blockIdx.x * GBN;
    const int iters = (K + 15) / 16;

    const int qr = l >> 2;   // groupID 0..7
    const int qc = l & 3;    // threadID-in-group 0..3

    // cp.async mappings
    const int a_row = tid >> 2;           // 0..63 (+64 on pass 2)
    const int a_kc  = (tid & 3) * 4;      // float chunk base within k-tile
    const int b_row = tid >> 1;           // 0..127
    const int b_ck  = (tid & 1) * 8;      // bf16 chunk base within k-tile
    const bool brok = (n0 + b_row) < Nc;
    const __nv_bfloat16* BhRow = Bh + (size_t)(brok ? n0 + b_row : 0) * Kpad;
    const __nv_bfloat16* BlRow = Bl + (size_t)(brok ? n0 + b_row : 0) * Kpad;

    float acc[2][8][4];
#pragma unroll
    for (int mi = 0; mi < 2; mi++)
#pragma unroll
        for (int ni = 0; ni < 8; ni++)
#pragma unroll
            for (int r = 0; r < 4; r++) acc[mi][ni][r] = 0.f;

    auto issue_load = [&](int it, int buf) {
        const int k0 = it * 16;
#pragma unroll
        for (int i = 0; i < 2; i++) {
            int row = a_row + i * 64;
            int gm = m0 + row, gk = k0 + a_kc;
            int ok = (gm < M) && (gk + 4 <= K);
            const float* src = A + (size_t)(ok ? gm : 0) * K + (ok ? gk : 0);
            uint32_t dst = (uint32_t)__cvta_generic_to_shared(&As[buf][row][a_kc]);
            cp_async16(dst, src, ok ? 16 : 0);
        }
        {
            uint32_t dsth = (uint32_t)__cvta_generic_to_shared(&BsH[buf][b_row][b_ck]);
            uint32_t dstl = (uint32_t)__cvta_generic_to_shared(&BsL[buf][b_row][b_ck]);
            cp_async16(dsth, BhRow + k0 + b_ck, brok ? 16 : 0);
            cp_async16(dstl, BlRow + k0 + b_ck, brok ? 16 : 0);
        }
        cp_commit();
    };

    issue_load(0, 0);

    for (int it = 0; it < iters; it++) {
        const int buf = it & 1;
        if (it + 1 < iters) {
            issue_load(it + 1, buf ^ 1);
            cp_wait<1>();
        } else {
            cp_wait<0>();
        }
        __syncthreads();

        // A fragments: split fp32 -> bf16 hi/lo in registers
        uint32_t ah[2][4], al[2][4];
#pragma unroll
        for (int mi = 0; mi < 2; mi++) {
            int r0 = wm + mi * 16 + qr;
            split_pack(*(float2*)&As[buf][r0][2 * qc],         ah[mi][0], al[mi][0]);
            split_pack(*(float2*)&As[buf][r0 + 8][2 * qc],     ah[mi][1], al[mi][1]);
            split_pack(*(float2*)&As[buf][r0][2 * qc + 8],     ah[mi][2], al[mi][2]);
            split_pack(*(float2*)&As[buf][r0 + 8][2 * qc + 8], ah[mi][3], al[mi][3]);
        }
        // B fragments (pre-split bf16)
        uint32_t bh[8][2], bl[8][2];
#pragma unroll
        for (int ni = 0; ni < 8; ni++) {
            int n = wn + ni * 8 + qr;
            bh[ni][0] = *(const uint32_t*)&BsH[buf][n][2 * qc];
            bh[ni][1] = *(const uint32_t*)&BsH[buf][n][2 * qc + 8];
            bl[ni][0] = *(const uint32_t*)&BsL[buf][n][2 * qc];
            bl[ni][1] = *(const uint32_t*)&BsL[buf][n][2 * qc + 8];
        }
#pragma unroll
        for (int mi = 0; mi < 2; mi++)
#pragma unroll
            for (int ni = 0; ni < 8; ni++) {
                mma_bf16(acc[mi][ni], ah[mi], bl[ni]);
                mma_bf16(acc[mi][ni], al[mi], bh[ni]);
                mma_bf16(acc[mi][ni], ah[mi], bh[ni]);
            }
        __syncthreads();
    }

    // -------- epilogue: bias -> BN -> (ReLU) (R4/R9-proven) --------
#pragma unroll
    for (int ni = 0; ni < 8; ni++) {
        int col = n0 + wn + ni * 8 + qc * 2;
        if (col >= Nc) continue;   // Nc even -> col+1 valid
        float bb0 = bias[col], bb1 = bias[col + 1];
        float ga0 = bnp[col],          be0 = bnp[Nc + col];
        float mu0 = bnp[2 * Nc + col], va0 = bnp[3 * Nc + col];
        float ga1 = bnp[col + 1],          be1 = bnp[Nc + col + 1];
        float mu1 = bnp[2 * Nc + col + 1], va1 = bnp[3 * Nc + col + 1];
        float s0 = ga0 * rsqrtf(va0 + EPS_BN), t0 = be0 - mu0 * s0;
        float s1 = ga1 * rsqrtf(va1 + EPS_BN), t1 = be1 - mu1 * s1;
#pragma unroll
        for (int mi = 0; mi < 2; mi++) {
#pragma unroll
            for (int r = 0; r < 2; r++) {
                int row = m0 + wm + mi * 16 + qr + r * 8;
                if (row >= M) continue;
                float v0 = (acc[mi][ni][r * 2 + 0] + bb0) * s0 + t0;
                float v1 = (acc[mi][ni][r * 2 + 1] + bb1) * s1 + t1;
                if (do_relu) { v0 = fmaxf(v0, 0.f); v1 = fmaxf(v1, 0.f); }
                *(float2*)(C + (size_t)row * Nc + col) = make_float2(v0, v1);
            }
        }
    }
}

static void run_gemm(const float* A, const __nv_bfloat16* Bh, const __nv_bfloat16* Bl,
                     const float* bias, const float* bnp, float* C,
                     int M, int K, int Kpad, int Nc, int do_relu) {
    dim3 grid((Nc + GBN - 1) / GBN, (M + GBM - 1) / GBM);
    gemm_bf16x3_bn<<<grid, 256>>>(A, Bh, Bl, bias, bnp, C, M, K, Kpad, Nc, do_relu);
}

// ---------------------------------------------------------------------------
// kernel_launch
// ---------------------------------------------------------------------------
extern "C" void kernel_launch(void* const* d_in, const int* in_sizes, int n_in,
                              void* d_out, int out_size) {
    const int*   x         = (const int*)  d_in[0];
    const int*   edge_idx  = (const int*)  d_in[1];
    const int*   edge_attr = (const int*)  d_in[2];
    const int*   batch     = (const int*)  d_in[3];
    const float* atom_emb  = (const float*)d_in[4];
    const float* bond_emb  = (const float*)d_in[5];
    const float* W1        = (const float*)d_in[6];
    const float* b1        = (const float*)d_in[7];
    const float* bn_in     = (const float*)d_in[8];
    const float* W2        = (const float*)d_in[9];
    const float* b2        = (const float*)d_in[10];
    const float* bn_out    = (const float*)d_in[11];
    const float* vn        = (const float*)d_in[12];
    const float* vW1       = (const float*)d_in[13];
    const float* vb1       = (const float*)d_in[14];
    const float* vbn1      = (const float*)d_in[15];
    const float* vW2       = (const float*)d_in[16];
    const float* vb2       = (const float*)d_in[17];
    const float* vbn2      = (const float*)d_in[18];
    float*       out       = (float*)d_out;

    const int N = in_sizes[0] / 9;
    const int E = in_sizes[1] / 2;
    const int G = out_size / DIM;

    float *h, *aggr, *hid, *post, *vfeat, *pooled, *vhid, *cnt;
    __nv_bfloat16 *W1h, *W1l, *W2h, *W2l, *vW1h, *vW1l, *vW2h, *vW2l;
    cudaGetSymbolAddress((void**)&h,      g_h);
    cudaGetSymbolAddress((void**)&aggr,   g_aggr);
    cudaGetSymbolAddress((void**)&hid,    g_hid);
    cudaGetSymbolAddress((void**)&post,   g_post);
    cudaGetSymbolAddress((void**)&vfeat,  g_vfeat);
    cudaGetSymbolAddress((void**)&pooled, g_pooled);
    cudaGetSymbolAddress((void**)&vhid,   g_vhid);
    cudaGetSymbolAddress((void**)&cnt,    g_cnt);
    cudaGetSymbolAddress((void**)&W1h,    g_W1h);
    cudaGetSymbolAddress((void**)&W1l,    g_W1l);
    cudaGetSymbolAddress((void**)&W2h,    g_W2h);
    cudaGetSymbolAddress((void**)&W2l,    g_W2l);
    cudaGetSymbolAddress((void**)&vW1h,   g_vW1h);
    cudaGetSymbolAddress((void**)&vW1l,   g_vW1l);
    cudaGetSymbolAddress((void**)&vW2h,   g_vW2h);
    cudaGetSymbolAddress((void**)&vW2l,   g_vW2l);

    const int* src = edge_idx;
    const int* dst = edge_idx + E;

    const int TPB = 256;
    const int nodeC4Blocks = (N * C4 + TPB - 1) / TPB;
    const int edgeC4Blocks = (E * C4 + TPB - 1) / TPB;

    // ---- per-call weight prep: split+transpose into bf16 hi/lo ----
    {
        int t1 = HID * KPAD1;   // per layer
        int t2 = DIM * KPAD2;
        for (int l = 0; l < NLAYER; l++) {
            split_w_t<<<(t1 + TPB - 1) / TPB, TPB>>>(
                W1 + (size_t)l * DIM * HID, W1h + (size_t)l * t1, W1l + (size_t)l * t1,
                DIM, HID, KPAD1);
            split_w_t<<<(t2 + TPB - 1) / TPB, TPB>>>(
                W2 + (size_t)l * HID * DIM, W2h + (size_t)l * t2, W2l + (size_t)l * t2,
                HID, DIM, KPAD2);
        }
        split_w_t<<<(t1 + TPB - 1) / TPB, TPB>>>(vW1, vW1h, vW1l, DIM, HID, KPAD1);
        split_w_t<<<(t2 + TPB - 1) / TPB, TPB>>>(vW2, vW2h, vW2l, HID, DIM, KPAD2);
    }

    atom_encode_kernel<<<nodeC4Blocks, TPB>>>(x, atom_emb, h, aggr, N);
    vfeat_init_kernel<<<(G * DIM + TPB - 1) / TPB, TPB>>>(vn, vfeat, G);
    cudaMemsetAsync(cnt, 0, (size_t)G * sizeof(float));
    count_kernel<<<(N + TPB - 1) / TPB, TPB>>>(batch, cnt, N);

    for (int l = 0; l < NLAYER; l++) {
        if (l > 0)
            add_vfeat_kernel<<<nodeC4Blocks, TPB>>>(post, vfeat, batch, h, aggr, N);

        // aggr holds h; edge atomics produce z = h + sum(msg)
        edge_msg_kernel<<<edgeC4Blocks, TPB>>>(
            h, src, dst, edge_attr, bond_emb + (size_t)l * 3 * 16 * DIM, aggr, E);

        // hid = relu(bn_in(z @ W1 + b1))
        run_gemm(aggr, W1h + (size_t)l * HID * KPAD1, W1l + (size_t)l * HID * KPAD1,
                 b1 + (size_t)l * HID, bn_in + (size_t)l * 4 * HID, hid,
                 N, DIM, KPAD1, HID, 1);
        // post = bn_out(hid @ W2 + b2) (+relu except last layer)
        run_gemm(hid, W2h + (size_t)l * DIM * KPAD2, W2l + (size_t)l * DIM * KPAD2,
                 b2 + (size_t)l * DIM, bn_out + (size_t)l * 4 * DIM, post,
                 N, HID, KPAD2, DIM, (l < NLAYER - 1) ? 1 : 0);

        if (l >= 1 && l < NLAYER - 1) {
            copy_kernel<<<(G * C4 + TPB - 1) / TPB, TPB>>>(vfeat, pooled, G * C4);
            pool_kernel<<<nodeC4Blocks, TPB>>>(post, batch, pooled, N);
            run_gemm(pooled, vW1h, vW1l, vb1, vbn1, vhid, G, DIM, KPAD1, HID, 1);
            run_gemm(vhid, vW2h, vW2l, vb2, vbn2, vfeat, G, HID, KPAD2, DIM, 1);
        }
    }

    cudaMemsetAsync(pooled, 0, (size_t)G * DIM * sizeof(float));
    pool_kernel<<<nodeC4Blocks, TPB>>>(post, batch, pooled, N);
    out_kernel<<<(G * DIM + TPB - 1) / TPB, TPB>>>(pooled, cnt, out, G);
}

// round 15
// speedup vs baseline: 1.4100x; 1.1580x over previous
#include <cuda_runtime.h>
#include <cuda_bf16.h>
#include <cstdint>

// ---------------------------------------------------------------------------
// vGINMolEncoder: 5-layer GINEConv + virtual node, eval-mode BN, mean-pool.
// GEMMs: bf16x3 mma.sync.m16n8k16 (R14-proven, untouched).
// Edge aggregation: dst-CSR built once per call; deterministic gather-sum
// replaces fp32 atomic scatter.
// ---------------------------------------------------------------------------

#define MAXN 200000
#define MAXE 800000
#define MAXG 8000
#define DIM  300
#define HID  600
#define NLAYER 5
#define EPS_BN 1e-5f
#define C4 75            // DIM / 4
#define KPAD1 304        // DIM padded to 16
#define KPAD2 608        // HID padded to 16
#define SCAN_B 256

__device__ __align__(256) float g_h     [(size_t)MAXN * DIM];
__device__ __align__(256) float g_aggr  [(size_t)MAXN * DIM];
__device__ __align__(256) float g_hid   [(size_t)MAXN * HID];
__device__ __align__(256) float g_post  [(size_t)MAXN * DIM];
__device__ __align__(256) float g_vfeat [(size_t)MAXG * DIM];
__device__ __align__(256) float g_pooled[(size_t)MAXG * DIM];
__device__ __align__(256) float g_vhid  [(size_t)MAXG * HID];
__device__ __align__(256) float g_cnt   [MAXG];
// CSR scratch
__device__ __align__(256) int g_deg     [MAXN];
__device__ __align__(256) int g_rowstart[MAXN + 1];
__device__ __align__(256) int g_cursor  [MAXN];
__device__ __align__(256) int g_btot    [1024];
__device__ __align__(256) int g_eid     [MAXE];
// bf16 hi/lo split weights, transposed: [Nc][Kpad]
__device__ __align__(256) __nv_bfloat16 g_W1h [(size_t)NLAYER * HID * KPAD1];
__device__ __align__(256) __nv_bfloat16 g_W1l [(size_t)NLAYER * HID * KPAD1];
__device__ __align__(256) __nv_bfloat16 g_W2h [(size_t)NLAYER * DIM * KPAD2];
__device__ __align__(256) __nv_bfloat16 g_W2l [(size_t)NLAYER * DIM * KPAD2];
__device__ __align__(256) __nv_bfloat16 g_vW1h[(size_t)HID * KPAD1];
__device__ __align__(256) __nv_bfloat16 g_vW1l[(size_t)HID * KPAD1];
__device__ __align__(256) __nv_bfloat16 g_vW2h[(size_t)DIM * KPAD2];
__device__ __align__(256) __nv_bfloat16 g_vW2l[(size_t)DIM * KPAD2];

// ---------------------------------------------------------------------------
// CSR construction (once per call; edge_index constant across layers)
// ---------------------------------------------------------------------------
__global__ void deg_count_kernel(const int* __restrict__ dst, int* __restrict__ deg, int E) {
    int e = blockIdx.x * blockDim.x + threadIdx.x;
    if (e < E) atomicAdd(&deg[dst[e]], 1);
}

// per-block exclusive scan; block totals out
__global__ void scan_block_kernel(const int* __restrict__ deg, int* __restrict__ rs,
                                  int* __restrict__ btot, int N) {
    __shared__ int s[SCAN_B];
    int i = blockIdx.x * SCAN_B + threadIdx.x;
    int v = (i < N) ? deg[i] : 0;
    s[threadIdx.x] = v;
    __syncthreads();
#pragma unroll
    for (int off = 1; off < SCAN_B; off <<= 1) {
        int t = (threadIdx.x >= off) ? s[threadIdx.x - off] : 0;
        __syncthreads();
        s[threadIdx.x] += t;
        __syncthreads();
    }
    if (i < N) rs[i] = s[threadIdx.x] - v;       // exclusive
    if (threadIdx.x == SCAN_B - 1) btot[blockIdx.x] = s[threadIdx.x];
}

// single-block exclusive scan of block totals (nb <= 1024)
__global__ void scan_total_kernel(int* __restrict__ btot, int nb) {
    __shared__ int s[1024];
    int v = (threadIdx.x < nb) ? btot[threadIdx.x] : 0;
    s[threadIdx.x] = v;
    __syncthreads();
#pragma unroll
    for (int off = 1; off < 1024; off <<= 1) {
        int t = (threadIdx.x >= off) ? s[threadIdx.x - off] : 0;
        __syncthreads();
        s[threadIdx.x] += t;
        __syncthreads();
    }
    if (threadIdx.x < nb) btot[threadIdx.x] = s[threadIdx.x] - v;   // exclusive
}

__global__ void add_offsets_kernel(int* __restrict__ rs, const int* __restrict__ btot,
                                   int N, int E) {
    int i = blockIdx.x * blockDim.x + threadIdx.x;
    if (i < N) rs[i] += btot[i / SCAN_B];
    if (i == 0) rs[N] = E;
}

__global__ void scatter_kernel(const int* __restrict__ dst, int* __restrict__ cursor,
                               int* __restrict__ eid, int E) {
    int e = blockIdx.x * blockDim.x + threadIdx.x;
    if (e >= E) return;
    int p = atomicAdd(&cursor[dst[e]], 1);
    eid[p] = e;
}

// ---------------------------------------------------------------------------
// Elementwise kernels
// ---------------------------------------------------------------------------
__global__ void atom_encode_kernel(const int* __restrict__ x,
                                   const float* __restrict__ atom_emb,
                                   float* __restrict__ h, int N) {
    int idx = blockIdx.x * blockDim.x + threadIdx.x;
    if (idx >= N * C4) return;
    int n = idx / C4;
    int c = (idx - n * C4) * 4;
    float4 s = make_float4(0.f, 0.f, 0.f, 0.f);
#pragma unroll
    for (int f = 0; f < 9; f++) {
        int v = x[n * 9 + f];
        const float4 e = *(const float4*)(atom_emb + ((size_t)(f * 64 + v)) * DIM + c);
        s.x += e.x; s.y += e.y; s.z += e.z; s.w += e.w;
    }
    *(float4*)(h + (size_t)n * DIM + c) = s;
}

// CSR edge aggregation: aggr[n] = h[n] + sum_{e: dst=n} relu(h[src] + bond(ea))
__global__ void edge_aggr_csr(const float* __restrict__ h,
                              const int* __restrict__ src,
                              const int* __restrict__ ea,
                              const float* __restrict__ bond_l,   // [3,16,DIM]
                              const int* __restrict__ rs,
                              const int* __restrict__ eid,
                              float* __restrict__ aggr, int N) {
    int idx = blockIdx.x * blockDim.x + threadIdx.x;
    if (idx >= N * C4) return;
    int n = idx / C4;
    int c = (idx - n * C4) * 4;
    float4 s = *(const float4*)(h + (size_t)n * DIM + c);
    int b = rs[n], en = rs[n + 1];
    for (int i = b; i < en; i++) {
        int e  = eid[i];
        int sn = src[e];
        int a0 = ea[e * 3 + 0], a1 = ea[e * 3 + 1], a2 = ea[e * 3 + 2];
        const float4 b0 = *(const float4*)(bond_l + ((size_t)(0 * 16 + a0)) * DIM + c);
        const float4 b1 = *(const float4*)(bond_l + ((size_t)(1 * 16 + a1)) * DIM + c);
        const float4 b2 = *(const float4*)(bond_l + ((size_t)(2 * 16 + a2)) * DIM + c);
        const float4 hv = *(const float4*)(h + (size_t)sn * DIM + c);
        s.x += fmaxf(hv.x + b0.x + b1.x + b2.x, 0.f);
        s.y += fmaxf(hv.y + b0.y + b1.y + b2.y, 0.f);
        s.z += fmaxf(hv.z + b0.z + b1.z + b2.z, 0.f);
        s.w += fmaxf(hv.w + b0.w + b1.w + b2.w, 0.f);
    }
    *(float4*)(aggr + (size_t)n * DIM + c) = s;
}

__global__ void add_vfeat_kernel(const float* __restrict__ post,
                                 const float* __restrict__ vfeat,
                                 const int* __restrict__ batch,
                                 float* __restrict__ h, int N) {
    int idx = blockIdx.x * blockDim.x + threadIdx.x;
    if (idx >= N * C4) return;
    int n = idx / C4;
    int c = (idx - n * C4) * 4;
    int g = batch[n];
    const float4 p = *(const float4*)(post  + (size_t)n * DIM + c);
    const float4 v = *(const float4*)(vfeat + (size_t)g * DIM + c);
    float4 o = make_float4(p.x + v.x, p.y + v.y, p.z + v.z, p.w + v.w);
    *(float4*)(h + (size_t)n * DIM + c) = o;
}

__global__ void pool_kernel(const float* __restrict__ post,
                            const int* __restrict__ batch,
                            float* __restrict__ pooled, int N) {
    int idx = blockIdx.x * blockDim.x + threadIdx.x;
    if (idx >= N * C4) return;
    int n = idx / C4;
    int c = (idx - n * C4) * 4;
    int g = batch[n];
    const float4 p = *(const float4*)(post + (size_t)n * DIM + c);
    float* q = pooled + (size_t)g * DIM + c;
    atomicAdd(q + 0, p.x);
    atomicAdd(q + 1, p.y);
    atomicAdd(q + 2, p.z);
    atomicAdd(q + 3, p.w);
}

__global__ void count_kernel(const int* __restrict__ batch, float* __restrict__ cnt, int N) {
    int i = blockIdx.x * blockDim.x + threadIdx.x;
    if (i < N) atomicAdd(&cnt[batch[i]], 1.0f);
}

__global__ void vfeat_init_kernel(const float* __restrict__ vn, float* __restrict__ vfeat, int G) {
    int idx = blockIdx.x * blockDim.x + threadIdx.x;
    if (idx >= G * DIM) return;
    vfeat[idx] = vn[idx % DIM];
}

__global__ void copy_kernel(const float* __restrict__ src, float* __restrict__ dst, int n4) {
    int idx = blockIdx.x * blockDim.x + threadIdx.x;
    if (idx >= n4) return;
    *(float4*)(dst + idx * 4) = *(const float4*)(src + idx * 4);
}

__global__ void out_kernel(const float* __restrict__ pooled, const float* __restrict__ cnt,
                           float* __restrict__ out, int G) {
    int idx = blockIdx.x * blockDim.x + threadIdx.x;
    if (idx >= G * DIM) return;
    int g = idx / DIM;
    out[idx] = pooled[idx] / fmaxf(cnt[g], 1.0f);
}

// W [K][Nc] row-major -> Wh/Wl [Nc][Kpad] bf16
__global__ void split_w_t(const float* __restrict__ W, __nv_bfloat16* __restrict__ Wh,
                          __nv_bfloat16* __restrict__ Wl, int K, int Nc, int Kpad) {
    int idx = blockIdx.x * blockDim.x + threadIdx.x;
    if (idx >= Nc * Kpad) return;
    int n = idx / Kpad;
    int k = idx - n * Kpad;
    float v = (k < K) ? W[(size_t)k * Nc + n] : 0.f;
    __nv_bfloat16 hh = __float2bfloat16_rn(v);
    __nv_bfloat16 ll = __float2bfloat16_rn(v - __bfloat162float(hh));
    Wh[idx] = hh;
    Wl[idx] = ll;
}

// ---------------------------------------------------------------------------
// bf16x3 GEMM with fused BN(+ReLU) epilogue (R14-proven, unchanged).
// ---------------------------------------------------------------------------
#define GBM 128
#define GBN 128
#define LDA 20
#define LDBH 24

__device__ __forceinline__ void cp_async16(uint32_t saddr, const void* gptr, int src_bytes) {
    asm volatile("cp.async.cg.shared.global [%0], [%1], 16, %2;\n"
                 :: "r"(saddr), "l"(gptr), "r"(src_bytes));
}
__device__ __forceinline__ void cp_commit() { asm volatile("cp.async.commit_group;\n" ::); }
template <int N>
__device__ __forceinline__ void cp_wait() { asm volatile("cp.async.wait_group %0;\n" :: "n"(N)); }

__device__ __forceinline__ void mma_bf16(float* d, const uint32_t* a, const uint32_t* b) {
    asm volatile(
        "mma.sync.aligned.m16n8k16.row.col.f32.bf16.bf16.f32 "
        "{%0,%1,%2,%3}, {%4,%5,%6,%7}, {%8,%9}, {%0,%1,%2,%3};\n"
        : "+f"(d[0]), "+f"(d[1]), "+f"(d[2]), "+f"(d[3])
        : "r"(a[0]), "r"(a[1]), "r"(a[2]), "r"(a[3]), "r"(b[0]), "r"(b[1]));
}

__device__ __forceinline__ void split_pack(float2 v, uint32_t& hi, uint32_t& lo) {
    __nv_bfloat16 hx = __float2bfloat16_rn(v.x), hy = __float2bfloat16_rn(v.y);
    __nv_bfloat16 lx = __float2bfloat16_rn(v.x - __bfloat162float(hx));
    __nv_bfloat16 ly = __float2bfloat16_rn(v.y - __bfloat162float(hy));
    __nv_bfloat162 H = __halves2bfloat162(hx, hy);
    __nv_bfloat162 L = __halves2bfloat162(lx, ly);
    hi = *(uint32_t*)&H;
    lo = *(uint32_t*)&L;
}

__global__ __launch_bounds__(256) void gemm_bf16x3_bn(
    const float* __restrict__ A, const __nv_bfloat16* __restrict__ Bh,
    const __nv_bfloat16* __restrict__ Bl,
    const float* __restrict__ bias, const float* __restrict__ bnp,
    float* __restrict__ C, int M, int K, int Kpad, int Nc, int do_relu) {

    __shared__ __align__(16) float         As [2][GBM][LDA];
    __shared__ __align__(16) __nv_bfloat16 BsH[2][GBN][LDBH];
    __shared__ __align__(16) __nv_bfloat16 BsL[2][GBN][LDBH];

    const int tid = threadIdx.x;
    const int w = tid >> 5, l = tid & 31;
    const int wm = (w & 3) * 32;
    const int wn = (w >> 2) * 64;
    const int m0 = blockIdx.y * GBM;
    const int n0 = blockIdx.x * GBN;
    const int iters = (K + 15) / 16;

    const int qr = l >> 2;
    const int qc = l & 3;

    const int a_row = tid >> 2;
    const int a_kc  = (tid & 3) * 4;
    const int b_row = tid >> 1;
    const int b_ck  = (tid & 1) * 8;
    const bool brok = (n0 + b_row) < Nc;
    const __nv_bfloat16* BhRow = Bh + (size_t)(brok ? n0 + b_row : 0) * Kpad;
    const __nv_bfloat16* BlRow = Bl + (size_t)(brok ? n0 + b_row : 0) * Kpad;

    float acc[2][8][4];
#pragma unroll
    for (int mi = 0; mi < 2; mi++)
#pragma unroll
        for (int ni = 0; ni < 8; ni++)
#pragma unroll
            for (int r = 0; r < 4; r++) acc[mi][ni][r] = 0.f;

    auto issue_load = [&](int it, int buf) {
        const int k0 = it * 16;
#pragma unroll
        for (int i = 0; i < 2; i++) {
            int row = a_row + i * 64;
            int gm = m0 + row, gk = k0 + a_kc;
            int ok = (gm < M) && (gk + 4 <= K);
            const float* src = A + (size_t)(ok ? gm : 0) * K + (ok ? gk : 0);
            uint32_t dst = (uint32_t)__cvta_generic_to_shared(&As[buf][row][a_kc]);
            cp_async16(dst, src, ok ? 16 : 0);
        }
        {
            uint32_t dsth = (uint32_t)__cvta_generic_to_shared(&BsH[buf][b_row][b_ck]);
            uint32_t dstl = (uint32_t)__cvta_generic_to_shared(&BsL[buf][b_row][b_ck]);
            cp_async16(dsth, BhRow + k0 + b_ck, brok ? 16 : 0);
            cp_async16(dstl, BlRow + k0 + b_ck, brok ? 16 : 0);
        }
        cp_commit();
    };

    issue_load(0, 0);

    for (int it = 0; it < iters; it++) {
        const int buf = it & 1;
        if (it + 1 < iters) {
            issue_load(it + 1, buf ^ 1);
            cp_wait<1>();
        } else {
            cp_wait<0>();
        }
        __syncthreads();

        uint32_t ah[2][4], al[2][4];
#pragma unroll
        for (int mi = 0; mi < 2; mi++) {
            int r0 = wm + mi * 16 + qr;
            split_pack(*(float2*)&As[buf][r0][2 * qc],         ah[mi][0], al[mi][0]);
            split_pack(*(float2*)&As[buf][r0 + 8][2 * qc],     ah[mi][1], al[mi][1]);
            split_pack(*(float2*)&As[buf][r0][2 * qc + 8],     ah[mi][2], al[mi][2]);
            split_pack(*(float2*)&As[buf][r0 + 8][2 * qc + 8], ah[mi][3], al[mi][3]);
        }
        uint32_t bh[8][2], bl[8][2];
#pragma unroll
        for (int ni = 0; ni < 8; ni++) {
            int n = wn + ni * 8 + qr;
            bh[ni][0] = *(const uint32_t*)&BsH[buf][n][2 * qc];
            bh[ni][1] = *(const uint32_t*)&BsH[buf][n][2 * qc + 8];
            bl[ni][0] = *(const uint32_t*)&BsL[buf][n][2 * qc];
            bl[ni][1] = *(const uint32_t*)&BsL[buf][n][2 * qc + 8];
        }
#pragma unroll
        for (int mi = 0; mi < 2; mi++)
#pragma unroll
            for (int ni = 0; ni < 8; ni++) {
                mma_bf16(acc[mi][ni], ah[mi], bl[ni]);
                mma_bf16(acc[mi][ni], al[mi], bh[ni]);
                mma_bf16(acc[mi][ni], ah[mi], bh[ni]);
            }
        __syncthreads();
    }

#pragma unroll
    for (int ni = 0; ni < 8; ni++) {
        int col = n0 + wn + ni * 8 + qc * 2;
        if (col >= Nc) continue;
        float bb0 = bias[col], bb1 = bias[col + 1];
        float ga0 = bnp[col],          be0 = bnp[Nc + col];
        float mu0 = bnp[2 * Nc + col], va0 = bnp[3 * Nc + col];
        float ga1 = bnp[col + 1],          be1 = bnp[Nc + col + 1];
        float mu1 = bnp[2 * Nc + col + 1], va1 = bnp[3 * Nc + col + 1];
        float s0 = ga0 * rsqrtf(va0 + EPS_BN), t0 = be0 - mu0 * s0;
        float s1 = ga1 * rsqrtf(va1 + EPS_BN), t1 = be1 - mu1 * s1;
#pragma unroll
        for (int mi = 0; mi < 2; mi++) {
#pragma unroll
            for (int r = 0; r < 2; r++) {
                int row = m0 + wm + mi * 16 + qr + r * 8;
                if (row >= M) continue;
                float v0 = (acc[mi][ni][r * 2 + 0] + bb0) * s0 + t0;
                float v1 = (acc[mi][ni][r * 2 + 1] + bb1) * s1 + t1;
                if (do_relu) { v0 = fmaxf(v0, 0.f); v1 = fmaxf(v1, 0.f); }
                *(float2*)(C + (size_t)row * Nc + col) = make_float2(v0, v1);
            }
        }
    }
}

static void run_gemm(const float* A, const __nv_bfloat16* Bh, const __nv_bfloat16* Bl,
                     const float* bias, const float* bnp, float* C,
                     int M, int K, int Kpad, int Nc, int do_relu) {
    dim3 grid((Nc + GBN - 1) / GBN, (M + GBM - 1) / GBM);
    gemm_bf16x3_bn<<<grid, 256>>>(A, Bh, Bl, bias, bnp, C, M, K, Kpad, Nc, do_relu);
}

// ---------------------------------------------------------------------------
// kernel_launch
// ---------------------------------------------------------------------------
extern "C" void kernel_launch(void* const* d_in, const int* in_sizes, int n_in,
                              void* d_out, int out_size) {
    const int*   x         = (const int*)  d_in[0];
    const int*   edge_idx  = (const int*)  d_in[1];
    const int*   edge_attr = (const int*)  d_in[2];
    const int*   batch     = (const int*)  d_in[3];
    const float* atom_emb  = (const float*)d_in[4];
    const float* bond_emb  = (const float*)d_in[5];
    const float* W1        = (const float*)d_in[6];
    const float* b1        = (const float*)d_in[7];
    const float* bn_in     = (const float*)d_in[8];
    const float* W2        = (const float*)d_in[9];
    const float* b2        = (const float*)d_in[10];
    const float* bn_out    = (const float*)d_in[11];
    const float* vn        = (const float*)d_in[12];
    const float* vW1       = (const float*)d_in[13];
    const float* vb1       = (const float*)d_in[14];
    const float* vbn1      = (const float*)d_in[15];
    const float* vW2       = (const float*)d_in[16];
    const float* vb2       = (const float*)d_in[17];
    const float* vbn2      = (const float*)d_in[18];
    float*       out       = (float*)d_out;

    const int N = in_sizes[0] / 9;
    const int E = in_sizes[1] / 2;
    const int G = out_size / DIM;

    float *h, *aggr, *hid, *post, *vfeat, *pooled, *vhid, *cnt;
    int *deg, *rowstart, *cursor, *btot, *eid;
    __nv_bfloat16 *W1h, *W1l, *W2h, *W2l, *vW1h, *vW1l, *vW2h, *vW2l;
    cudaGetSymbolAddress((void**)&h,        g_h);
    cudaGetSymbolAddress((void**)&aggr,     g_aggr);
    cudaGetSymbolAddress((void**)&hid,      g_hid);
    cudaGetSymbolAddress((void**)&post,     g_post);
    cudaGetSymbolAddress((void**)&vfeat,    g_vfeat);
    cudaGetSymbolAddress((void**)&pooled,   g_pooled);
    cudaGetSymbolAddress((void**)&vhid,     g_vhid);
    cudaGetSymbolAddress((void**)&cnt,      g_cnt);
    cudaGetSymbolAddress((void**)&deg,      g_deg);
    cudaGetSymbolAddress((void**)&rowstart, g_rowstart);
    cudaGetSymbolAddress((void**)&cursor,   g_cursor);
    cudaGetSymbolAddress((void**)&btot,     g_btot);
    cudaGetSymbolAddress((void**)&eid,      g_eid);
    cudaGetSymbolAddress((void**)&W1h,      g_W1h);
    cudaGetSymbolAddress((void**)&W1l,      g_W1l);
    cudaGetSymbolAddress((void**)&W2h,      g_W2h);
    cudaGetSymbolAddress((void**)&W2l,      g_W2l);
    cudaGetSymbolAddress((void**)&vW1h,     g_vW1h);
    cudaGetSymbolAddress((void**)&vW1l,     g_vW1l);
    cudaGetSymbolAddress((void**)&vW2h,     g_vW2h);
    cudaGetSymbolAddress((void**)&vW2l,     g_vW2l);

    const int* src = edge_idx;
    const int* dst = edge_idx + E;

    const int TPB = 256;
    const int nodeC4Blocks = (N * C4 + TPB - 1) / TPB;
    const int scanBlocks = (N + SCAN_B - 1) / SCAN_B;   // 782 <= 1024

    // ---- CSR build (once) ----
    cudaMemsetAsync(deg, 0, (size_t)N * sizeof(int));
    deg_count_kernel<<<(E + TPB - 1) / TPB, TPB>>>(dst, deg, E);
    scan_block_kernel<<<scanBlocks, SCAN_B>>>(deg, rowstart, btot, N);
    scan_total_kernel<<<1, 1024>>>(btot, scanBlocks);
    add_offsets_kernel<<<(N + TPB - 1) / TPB, TPB>>>(rowstart, btot, N, E);
    cudaMemcpyAsync(cursor, rowstart, (size_t)N * sizeof(int), cudaMemcpyDeviceToDevice);
    scatter_kernel<<<(E + TPB - 1) / TPB, TPB>>>(dst, cursor, eid, E);

    // ---- weight prep: split+transpose into bf16 hi/lo ----
    {
        int t1 = HID * KPAD1;
        int t2 = DIM * KPAD2;
        for (int l = 0; l < NLAYER; l++) {
            split_w_t<<<(t1 + TPB - 1) / TPB, TPB>>>(
                W1 + (size_t)l * DIM * HID, W1h + (size_t)l * t1, W1l + (size_t)l * t1,
                DIM, HID, KPAD1);
            split_w_t<<<(t2 + TPB - 1) / TPB, TPB>>>(
                W2 + (size_t)l * HID * DIM, W2h + (size_t)l * t2, W2l + (size_t)l * t2,
                HID, DIM, KPAD2);
        }
        split_w_t<<<(t1 + TPB - 1) / TPB, TPB>>>(vW1, vW1h, vW1l, DIM, HID, KPAD1);
        split_w_t<<<(t2 + TPB - 1) / TPB, TPB>>>(vW2, vW2h, vW2l, HID, DIM, KPAD2);
    }

    atom_encode_kernel<<<nodeC4Blocks, TPB>>>(x, atom_emb, h, N);
    vfeat_init_kernel<<<(G * DIM + TPB - 1) / TPB, TPB>>>(vn, vfeat, G);
    cudaMemsetAsync(cnt, 0, (size_t)G * sizeof(float));
    count_kernel<<<(N + TPB - 1) / TPB, TPB>>>(batch, cnt, N);

    for (int l = 0; l < NLAYER; l++) {
        if (l > 0)
            add_vfeat_kernel<<<nodeC4Blocks, TPB>>>(post, vfeat, batch, h, N);

        // aggr = h + sum of edge messages (CSR, deterministic)
        edge_aggr_csr<<<nodeC4Blocks, TPB>>>(
            h, src, edge_attr, bond_emb + (size_t)l * 3 * 16 * DIM,
            rowstart, eid, aggr, N);

        // hid = relu(bn_in(z @ W1 + b1))
        run_gemm(aggr, W1h + (size_t)l * HID * KPAD1, W1l + (size_t)l * HID * KPAD1,
                 b1 + (size_t)l * HID, bn_in + (size_t)l * 4 * HID, hid,
                 N, DIM, KPAD1, HID, 1);
        // post = bn_out(hid @ W2 + b2) (+relu except last layer)
        run_gemm(hid, W2h + (size_t)l * DIM * KPAD2, W2l + (size_t)l * DIM * KPAD2,
                 b2 + (size_t)l * DIM, bn_out + (size_t)l * 4 * DIM, post,
                 N, HID, KPAD2, DIM, (l < NLAYER - 1) ? 1 : 0);

        if (l >= 1 && l < NLAYER - 1) {
            copy_kernel<<<(G * C4 + TPB - 1) / TPB, TPB>>>(vfeat, pooled, G * C4);
            pool_kernel<<<nodeC4Blocks, TPB>>>(post, batch, pooled, N);
            run_gemm(pooled, vW1h, vW1l, vb1, vbn1, vhid, G, DIM, KPAD1, HID, 1);
            run_gemm(vhid, vW2h, vW2l, vb2, vbn2, vfeat, G, HID, KPAD2, DIM, 1);
        }
    }

    cudaMemsetAsync(pooled, 0, (size_t)G * DIM * sizeof(float));
    pool_kernel<<<nodeC4Blocks, TPB>>>(post, batch, pooled, N);
    out_kernel<<<(G * DIM + TPB - 1) / TPB, TPB>>>(pooled, cnt, out, G);
}